// round 5
// baseline (speedup 1.0000x reference)
#include <cuda_runtime.h>
#include <cstdint>

// Problem: out[N=100000,128] = zeros; out[i1]+=deltas[:,:128]; out[i2]+=deltas[:,128:256];
//          b = deltas[:,256:320].  d_out layout: [ out : N*128 fp32 ][ b : E*64 fp32 ]
//
// R4: TMA bulk-reduce scatter (as R3) with (a) LDGs hoisted above the
// buffer-availability wait so global-load latency overlaps the TMA drain, and
// (b) a 4-deep per-warp buffer ring (wait_group.read 3) so the wait rarely blocks.

#define WARPS_PER_BLOCK 8
#define THREADS_PER_BLOCK (WARPS_PER_BLOCK * 32)
#define STAGES 4

__device__ __forceinline__ uint64_t make_evict_last_policy() {
    uint64_t pol;
    asm("createpolicy.fractional.L2::evict_last.b64 %0, 1.0;" : "=l"(pol));
    return pol;
}

__device__ __forceinline__ uint64_t make_evict_first_policy() {
    uint64_t pol;
    asm("createpolicy.fractional.L2::evict_first.b64 %0, 1.0;" : "=l"(pol));
    return pol;
}

__global__ void zero_out_kernel(float4* __restrict__ out4, long n4) {
    long i = blockIdx.x * (long)blockDim.x + threadIdx.x;
    if (i < n4) {
        uint64_t pol = make_evict_last_policy();
        asm volatile("st.global.L2::cache_hint.v4.f32 [%0], {%1,%2,%3,%4}, %5;"
                     :: "l"(out4 + i), "f"(0.f), "f"(0.f), "f"(0.f), "f"(0.f), "l"(pol)
                     : "memory");
    }
}

__device__ __forceinline__ float4 ldg_stream(const float4* p, uint64_t pol) {
    float4 v;
    asm("ld.global.nc.L2::cache_hint.v4.f32 {%0,%1,%2,%3}, [%4], %5;"
        : "=f"(v.x), "=f"(v.y), "=f"(v.z), "=f"(v.w) : "l"(p), "l"(pol));
    return v;
}

__device__ __forceinline__ void stg_stream(float4* p, float4 v) {
    asm volatile("st.global.cs.v4.f32 [%0], {%1,%2,%3,%4};"
                 :: "l"(p), "f"(v.x), "f"(v.y), "f"(v.z), "f"(v.w)
                 : "memory");
}

__device__ __forceinline__ void bulk_reduce_add_f32(float* gdst, uint32_t ssrc,
                                                    uint32_t bytes, uint64_t pol) {
    asm volatile(
        "cp.reduce.async.bulk.global.shared::cta.bulk_group.L2::cache_hint.add.f32 "
        "[%0], [%1], %2, %3;"
        :: "l"(gdst), "r"(ssrc), "r"(bytes), "l"(pol)
        : "memory");
}

__global__ void __launch_bounds__(THREADS_PER_BLOCK)
scatter_kernel(const float4* __restrict__ deltas4,  // E * 80 float4
               const int*    __restrict__ i1,       // E
               const int*    __restrict__ i2,       // E
               float*        __restrict__ out,      // N * 128 fp32
               float4*       __restrict__ bout4,    // E * 16 float4
               long E, long nwarps)
{
    // Per-warp 4-deep buffer ring: STAGES x 64 float4 = 4 KB/warp.
    __shared__ __align__(16) float4 buf[WARPS_PER_BLOCK][STAGES][64];

    const int wid  = threadIdx.x >> 5;
    const int lane = threadIdx.x & 31;
    const long gw  = (long)blockIdx.x * WARPS_PER_BLOCK + wid;

    const uint64_t pol_ef = make_evict_first_policy();
    const uint64_t pol_el = make_evict_last_policy();

    int stage = 0;
    for (long e = gw; e < E; e += nwarps, stage = (stage + 1) & (STAGES - 1)) {
        const float4* row = deltas4 + e * 80;

        // Issue ALL independent loads first — their latency overlaps the
        // TMA-drain wait below.
        float4 v0 = ldg_stream(row + lane,      pol_ef);   // ux
        float4 v1 = ldg_stream(row + 32 + lane, pol_ef);   // uy
        float4 vb;
        if (lane < 16) vb = ldg_stream(row + 64 + lane, pol_ef);  // b
        int r1 = __ldg(&i1[e]);
        int r2 = __ldg(&i2[e]);

        // b goes straight out, independent of the buffer ring.
        if (lane < 16) stg_stream(bout4 + e * 16 + lane, vb);

        // Reclaim this stage's buffer: allow at most STAGES-1 groups with
        // unread sources.
        if (lane == 0)
            asm volatile("cp.async.bulk.wait_group.read %0;" :: "n"(STAGES - 1) : "memory");
        __syncwarp();

        buf[wid][stage][lane]      = v0;
        buf[wid][stage][32 + lane] = v1;
        __syncwarp();

        if (lane == 0) {
            asm volatile("fence.proxy.async.shared::cta;" ::: "memory");
            uint32_t s = (uint32_t)__cvta_generic_to_shared(&buf[wid][stage][0]);
            bulk_reduce_add_f32(out + (long)r1 * 128, s,       512, pol_el);
            bulk_reduce_add_f32(out + (long)r2 * 128, s + 512, 512, pol_el);
            asm volatile("cp.async.bulk.commit_group;" ::: "memory");
        }
    }

    // Drain all pending bulk groups before exit.
    if (lane == 0)
        asm volatile("cp.async.bulk.wait_group 0;" ::: "memory");
}

extern "C" void kernel_launch(void* const* d_in, const int* in_sizes, int n_in,
                              void* d_out, int out_size)
{
    // metadata order: unary(N*128 f32), binary(E*64 f32), deltas(E*320 f32),
    //                 index1(E i32), index2(E i32)
    const long N = in_sizes[0] / 128;
    const long E = in_sizes[2] / 320;

    const float4* deltas4 = (const float4*)d_in[2];
    const int*    i1      = (const int*)d_in[3];
    const int*    i2      = (const int*)d_in[4];

    float*  out   = (float*)d_out;                       // N*128
    float4* bout4 = (float4*)((float*)d_out + N * 128);  // E*16 float4

    // 1) zero the scatter target and pin it in L2 (evict_last)
    {
        long n4 = (N * 128) / 4;
        int  threads = 256;
        long blocks = (n4 + threads - 1) / threads;
        zero_out_kernel<<<(unsigned)blocks, threads>>>((float4*)out, n4);
    }

    // 2) scatter-add (TMA bulk-reduce, pipelined) + b copy
    {
        int  blocks = 2048;                       // 16384 warps, ~30 edges each
        long nwarps = (long)blocks * WARPS_PER_BLOCK;
        scatter_kernel<<<blocks, THREADS_PER_BLOCK>>>(deltas4, i1, i2, out, bout4, E, nwarps);
    }
}

// round 6
// speedup vs baseline: 1.0436x; 1.0436x over previous
#include <cuda_runtime.h>
#include <cstdint>

// Problem: out[N=100000,128] = zeros; out[i1]+=deltas[:,:128]; out[i2]+=deltas[:,128:256];
//          b = deltas[:,256:320].  d_out layout: [ out : N*128 fp32 ][ b : E*64 fp32 ]
//
// R5: R3's TMA bulk-reduce scatter (2-stage ring, 16KB smem, occ ~95%) with the
// LDGs + index loads hoisted ABOVE the wait_group so global-load latency overlaps
// the TMA drain. R4 showed deeper rings kill occupancy (33KB smem -> occ 65%) and
// lose more than the pipelining gains.

#define WARPS_PER_BLOCK 8
#define THREADS_PER_BLOCK (WARPS_PER_BLOCK * 32)
#define STAGES 2

__device__ __forceinline__ uint64_t make_evict_last_policy() {
    uint64_t pol;
    asm("createpolicy.fractional.L2::evict_last.b64 %0, 1.0;" : "=l"(pol));
    return pol;
}

__device__ __forceinline__ uint64_t make_evict_first_policy() {
    uint64_t pol;
    asm("createpolicy.fractional.L2::evict_first.b64 %0, 1.0;" : "=l"(pol));
    return pol;
}

__global__ void zero_out_kernel(float4* __restrict__ out4, long n4) {
    long i = blockIdx.x * (long)blockDim.x + threadIdx.x;
    if (i < n4) {
        uint64_t pol = make_evict_last_policy();
        asm volatile("st.global.L2::cache_hint.v4.f32 [%0], {%1,%2,%3,%4}, %5;"
                     :: "l"(out4 + i), "f"(0.f), "f"(0.f), "f"(0.f), "f"(0.f), "l"(pol)
                     : "memory");
    }
}

__device__ __forceinline__ float4 ldg_stream(const float4* p, uint64_t pol) {
    float4 v;
    asm("ld.global.nc.L2::cache_hint.v4.f32 {%0,%1,%2,%3}, [%4], %5;"
        : "=f"(v.x), "=f"(v.y), "=f"(v.z), "=f"(v.w) : "l"(p), "l"(pol));
    return v;
}

__device__ __forceinline__ void stg_stream(float4* p, float4 v) {
    asm volatile("st.global.cs.v4.f32 [%0], {%1,%2,%3,%4};"
                 :: "l"(p), "f"(v.x), "f"(v.y), "f"(v.z), "f"(v.w)
                 : "memory");
}

__device__ __forceinline__ void bulk_reduce_add_f32(float* gdst, uint32_t ssrc,
                                                    uint32_t bytes, uint64_t pol) {
    asm volatile(
        "cp.reduce.async.bulk.global.shared::cta.bulk_group.L2::cache_hint.add.f32 "
        "[%0], [%1], %2, %3;"
        :: "l"(gdst), "r"(ssrc), "r"(bytes), "l"(pol)
        : "memory");
}

__global__ void __launch_bounds__(THREADS_PER_BLOCK)
scatter_kernel(const float4* __restrict__ deltas4,  // E * 80 float4
               const int*    __restrict__ i1,       // E
               const int*    __restrict__ i2,       // E
               float*        __restrict__ out,      // N * 128 fp32
               float4*       __restrict__ bout4,    // E * 16 float4
               long E, long nwarps)
{
    // Per-warp 2-stage buffer ring: 2 x 64 float4 = 2 KB/warp, 16 KB/block.
    __shared__ __align__(16) float4 buf[WARPS_PER_BLOCK][STAGES][64];

    const int wid  = threadIdx.x >> 5;
    const int lane = threadIdx.x & 31;
    const long gw  = (long)blockIdx.x * WARPS_PER_BLOCK + wid;

    const uint64_t pol_ef = make_evict_first_policy();
    const uint64_t pol_el = make_evict_last_policy();

    int stage = 0;
    for (long e = gw; e < E; e += nwarps, stage ^= 1) {
        const float4* row = deltas4 + e * 80;

        // Issue ALL independent loads first — their latency overlaps the
        // TMA-drain wait below.
        float4 v0 = ldg_stream(row + lane,      pol_ef);   // ux
        float4 v1 = ldg_stream(row + 32 + lane, pol_ef);   // uy
        float4 vb;
        if (lane < 16) vb = ldg_stream(row + 64 + lane, pol_ef);  // b
        int r1 = __ldg(&i1[e]);
        int r2 = __ldg(&i2[e]);

        // b goes straight out, independent of the buffer ring.
        if (lane < 16) stg_stream(bout4 + e * 16 + lane, vb);

        // Reclaim this stage's buffer (handed to TMA 2 iterations ago).
        if (lane == 0)
            asm volatile("cp.async.bulk.wait_group.read %0;" :: "n"(STAGES - 1) : "memory");
        __syncwarp();

        buf[wid][stage][lane]      = v0;
        buf[wid][stage][32 + lane] = v1;
        __syncwarp();

        if (lane == 0) {
            asm volatile("fence.proxy.async.shared::cta;" ::: "memory");
            uint32_t s = (uint32_t)__cvta_generic_to_shared(&buf[wid][stage][0]);
            bulk_reduce_add_f32(out + (long)r1 * 128, s,       512, pol_el);
            bulk_reduce_add_f32(out + (long)r2 * 128, s + 512, 512, pol_el);
            asm volatile("cp.async.bulk.commit_group;" ::: "memory");
        }
    }

    // Drain all pending bulk groups before exit.
    if (lane == 0)
        asm volatile("cp.async.bulk.wait_group 0;" ::: "memory");
}

extern "C" void kernel_launch(void* const* d_in, const int* in_sizes, int n_in,
                              void* d_out, int out_size)
{
    // metadata order: unary(N*128 f32), binary(E*64 f32), deltas(E*320 f32),
    //                 index1(E i32), index2(E i32)
    const long N = in_sizes[0] / 128;
    const long E = in_sizes[2] / 320;

    const float4* deltas4 = (const float4*)d_in[2];
    const int*    i1      = (const int*)d_in[3];
    const int*    i2      = (const int*)d_in[4];

    float*  out   = (float*)d_out;                       // N*128
    float4* bout4 = (float4*)((float*)d_out + N * 128);  // E*16 float4

    // 1) zero the scatter target and pin it in L2 (evict_last)
    {
        long n4 = (N * 128) / 4;
        int  threads = 256;
        long blocks = (n4 + threads - 1) / threads;
        zero_out_kernel<<<(unsigned)blocks, threads>>>((float4*)out, n4);
    }

    // 2) scatter-add (TMA bulk-reduce, pipelined) + b copy
    {
        int  blocks = 2048;                       // 16384 warps, ~30 edges each
        long nwarps = (long)blocks * WARPS_PER_BLOCK;
        scatter_kernel<<<blocks, THREADS_PER_BLOCK>>>(deltas4, i1, i2, out, bout4, E, nwarps);
    }
}